// round 11
// baseline (speedup 1.0000x reference)
#include <cuda_runtime.h>

#define NN 100000
#define EE 1600000
#define GG 512
#define XD 79
#define HH 64
#define ST 36    // weight smem [c][kp] stride in uint32
#define AST 36   // sAgg stride in uint2 per node (72 words, 72%32==8 -> conflict-free)

// ---------------- scratch (static __device__, no allocations) ----------------
__device__ float d_h0[NN * HH];       // fp32 h, buffer 0 (proj output; final after 8 layers)
__device__ float d_h1[NN * HH];       // fp32 h, buffer 1
__device__ uint2 d_hp0[NN * 32];      // packed {bf16x2 hi, bf16x2 lo}, buffer 0
__device__ uint2 d_hp1[NN * 32];      // buffer 1
__device__ float d_Wc[8 * 192 * 64];
__device__ int   d_deg[NN];
__device__ int   d_rowptr[NN + 1];
__device__ int   d_cursor[NN];
__device__ int   d_col[EE + 8];
__device__ float d_pooled[GG * HH];
__device__ float d_cnt[GG];

// ---------------- helpers ----------------
__device__ __forceinline__ unsigned pack_bf16(float x, float y) {
    unsigned r; asm("cvt.rn.bf16x2.f32 %0, %1, %2;" : "=r"(r) : "f"(y), "f"(x)); return r;
}
__device__ __forceinline__ float bf_lo(unsigned p) { return __uint_as_float(p << 16); }
__device__ __forceinline__ float bf_hi(unsigned p) { return __uint_as_float(p & 0xFFFF0000u); }
__device__ __forceinline__ uint2 split2(float x, float y) {
    unsigned hi = pack_bf16(x, y);
    unsigned lo = pack_bf16(x - bf_lo(hi), y - bf_hi(hi));
    return make_uint2(hi, lo);
}
__device__ __forceinline__ void mma_bf16(float* d, const unsigned* a, const unsigned* b) {
    asm("mma.sync.aligned.m16n8k16.row.col.f32.bf16.bf16.f32 "
        "{%0,%1,%2,%3}, {%4,%5,%6,%7}, {%8,%9}, {%0,%1,%2,%3};"
        : "+f"(d[0]), "+f"(d[1]), "+f"(d[2]), "+f"(d[3])
        : "r"(a[0]), "r"(a[1]), "r"(a[2]), "r"(a[3]), "r"(b[0]), "r"(b[1]));
}
__device__ __forceinline__ float sigf(float x) { return 1.0f / (1.0f + __expf(-x)); }

// ---------------- init / CSR build ----------------
__global__ void k_zero() {
    int t = blockIdx.x * blockDim.x + threadIdx.x;
    if (t < NN) d_deg[t] = 0;
    if (t < GG * HH) d_pooled[t] = 0.0f;
    if (t < GG) d_cnt[t] = 0.0f;
}

__global__ void k_count(const int* __restrict__ ei) {
    int e = blockIdx.x * blockDim.x + threadIdx.x;
    if (e < EE) atomicAdd(&d_deg[ei[EE + e]], 1);
}

__global__ void k_scan() {
    __shared__ int wsum[32];
    __shared__ int carry;
    int t = threadIdx.x, lane = t & 31, wid = t >> 5;
    if (t == 0) carry = 0;
    __syncthreads();
    for (int base = 0; base < NN; base += 1024) {
        int i = base + t;
        int v = (i < NN) ? d_deg[i] : 0;
        int incl = v;
        #pragma unroll
        for (int o = 1; o < 32; o <<= 1) {
            int u = __shfl_up_sync(0xffffffffu, incl, o);
            if (lane >= o) incl += u;
        }
        if (lane == 31) wsum[wid] = incl;
        __syncthreads();
        if (wid == 0) {
            int si = wsum[lane];
            #pragma unroll
            for (int o = 1; o < 32; o <<= 1) {
                int u = __shfl_up_sync(0xffffffffu, si, o);
                if (lane >= o) si += u;
            }
            wsum[lane] = si;
        }
        __syncthreads();
        int off = (wid ? wsum[wid - 1] : 0) + carry;
        int total = wsum[31];
        if (i < NN) {
            d_rowptr[i + 1] = off + incl;
            d_cursor[i] = off + incl - v;
        }
        __syncthreads();
        if (t == 0) carry += total;
        __syncthreads();
    }
    if (t == 0) d_rowptr[0] = 0;
}

__global__ void k_fill(const int* __restrict__ ei) {
    int e = blockIdx.x * blockDim.x + threadIdx.x;
    if (e < EE) {
        int dst = ei[EE + e];
        int p = atomicAdd(&d_cursor[dst], 1);
        d_col[p] = ei[e];
    }
}

// ---------------- Wc[b,l] = ggc_W[b,l] @ gru_Wih[b]^T  (precompute, [c][k]) ----------------
__global__ void k_wc(const float* __restrict__ ggcW, const float* __restrict__ gWih) {
    int mat = blockIdx.x, b = mat >> 1;
    const float* W   = ggcW + mat * 4096;
    const float* Wih = gWih + b * 12288;
    __shared__ float sWt[4096];
    int t = threadIdx.x;
    for (int e = t; e < 4096; e += 256) sWt[(e & 63) * 64 + (e >> 6)] = W[e];
    __syncthreads();
    int cbase = blockIdx.y * 32;
    for (int e = t; e < 32 * 64; e += 256) {
        int c = cbase + (e >> 6), k = e & 63;
        const float* ir = Wih + c * 64;
        float s = 0.f;
        #pragma unroll 16
        for (int j = 0; j < 64; j++) s += sWt[j * 64 + k] * ir[j];
        d_Wc[mat * 12288 + c * 64 + k] = s;
    }
}

// ---------------- input projection: h = x @ Wp^T + bp  -> buffers 0 ----------------
__global__ void k_proj(const float* __restrict__ x, const float* __restrict__ Wp,
                       const float* __restrict__ bp) {
    __shared__ float2 sw[XD * 32];
    int t = threadIdx.x;
    for (int e = t; e < XD * 32; e += blockDim.x) {
        int k = e >> 5, L = e & 31;
        sw[e] = make_float2(Wp[(2 * L) * XD + k], Wp[(2 * L + 1) * XD + k]);
    }
    __syncthreads();
    int lane = t & 31;
    int w = blockIdx.x * (blockDim.x >> 5) + (t >> 5);
    int nw = gridDim.x * (blockDim.x >> 5);
    float bx = bp[2 * lane], by = bp[2 * lane + 1];
    for (int n = w; n < NN; n += nw) {
        const float* xr = x + n * XD;
        float ax = bx, ay = by;
        #pragma unroll 8
        for (int k = 0; k < XD; k++) {
            float xv = __ldg(&xr[k]);
            float2 wv = sw[k * 32 + lane];
            ax += wv.x * xv;
            ay += wv.y * xv;
        }
        ((float2*)(d_h0 + n * HH))[lane] = make_float2(ax, ay);
        d_hp0[n * 32 + lane] = split2(ax, ay);
    }
}

// ---------------- fused layer: aggregate (phase A) + GRU MMA/gates (phase B) ----------------
// Double-buffered: reads h_old/hp_old (parity), writes h_new/hp_new (1-parity).
// Phase A: warp wl gathers 4 nodes (R7 aggregate loop), split2 -> smem sAgg.
// Phase B: R7 MMA layout (mhalf = wl>>2, wq = wl&3), agg A-frags from smem.
__global__ void __launch_bounds__(512, 1) k_layer(int mat, const float* __restrict__ Whh,
                                                  const float* __restrict__ bih,
                                                  const float* __restrict__ bhh,
                                                  int parity, int dorelu) {
    extern __shared__ unsigned smu[];
    unsigned* WcHi = smu;
    unsigned* WcLo = smu + 192 * ST;
    unsigned* WhHi = smu + 2 * 192 * ST;
    unsigned* WhLo = smu + 3 * 192 * ST;
    uint2* sAgg = (uint2*)(smu + 4 * 192 * ST);   // [64 nodes][AST]

    const float* hsrc  = parity ? d_h1 : d_h0;
    const uint2* hpsrc = parity ? d_hp1 : d_hp0;
    float*       hdst  = parity ? d_h0 : d_h1;
    uint2*       hpdst = parity ? d_hp0 : d_hp1;

    const float* Wc = d_Wc + mat * 12288;
    int t = threadIdx.x;
    for (int e = t; e < 192 * 32; e += 512) {
        int c = e >> 5, kp = e & 31;
        float a0 = Wc[c * 64 + 2 * kp], a1 = Wc[c * 64 + 2 * kp + 1];
        uint2 pa = split2(a0, a1);
        WcHi[c * ST + kp] = pa.x;
        WcLo[c * ST + kp] = pa.y;
        float b0 = Whh[c * 64 + 2 * kp], b1 = Whh[c * 64 + 2 * kp + 1];
        uint2 pb = split2(b0, b1);
        WhHi[c * ST + kp] = pb.x;
        WhLo[c * ST + kp] = pb.y;
    }
    __syncthreads();
    int lane = t & 31, wl = t >> 5;
    int g = lane >> 2, tig = lane & 3;
    int mhalf = wl >> 2, wq = wl & 3;

    int cb0[3][2];
    #pragma unroll
    for (int gt = 0; gt < 3; gt++)
        #pragma unroll
        for (int j = 0; j < 2; j++)
            cb0[gt][j] = (gt * 64 + wq * 16 + j * 8 + g) * ST + tig;

    float bi[3][2][2], bh_[3][2][2];
    #pragma unroll
    for (int gt = 0; gt < 3; gt++)
        #pragma unroll
        for (int j = 0; j < 2; j++) {
            int col = gt * 64 + wq * 16 + j * 8 + 2 * tig;
            bi[gt][j][0] = __ldg(&bih[col]); bi[gt][j][1] = __ldg(&bih[col + 1]);
            bh_[gt][j][0] = __ldg(&bhh[col]); bh_[gt][j][1] = __ldg(&bhh[col + 1]);
        }

    for (int tile = blockIdx.x; tile * 64 < NN; tile += gridDim.x) {
        __syncthreads();   // sAgg of previous tile fully consumed before rewrite

        // ---- Phase A: gather-sum 4 nodes per warp into sAgg ----
        #pragma unroll
        for (int i = 0; i < 4; i++) {
            int node = tile * 64 + wl * 4 + i;
            if (node < NN) {
                int e0 = d_rowptr[node], e1 = d_rowptr[node + 1];
                float2 a0 = make_float2(0.f, 0.f), a1 = make_float2(0.f, 0.f);
                float2 a2 = make_float2(0.f, 0.f), a3 = make_float2(0.f, 0.f);
                int e = e0;
                for (; e < e1 && (e & 3); e++) {
                    int s = __ldg(&d_col[e]);
                    float2 v = ((const float2*)(hsrc + s * HH))[lane];
                    a0.x += v.x; a0.y += v.y;
                }
                for (; e + 4 <= e1; e += 4) {
                    int4 s4 = *reinterpret_cast<const int4*>(&d_col[e]);
                    float2 v0 = ((const float2*)(hsrc + s4.x * HH))[lane];
                    float2 v1 = ((const float2*)(hsrc + s4.y * HH))[lane];
                    float2 v2 = ((const float2*)(hsrc + s4.z * HH))[lane];
                    float2 v3 = ((const float2*)(hsrc + s4.w * HH))[lane];
                    a0.x += v0.x; a0.y += v0.y;
                    a1.x += v1.x; a1.y += v1.y;
                    a2.x += v2.x; a2.y += v2.y;
                    a3.x += v3.x; a3.y += v3.y;
                }
                for (; e < e1; e++) {
                    int s = __ldg(&d_col[e]);
                    float2 v = ((const float2*)(hsrc + s * HH))[lane];
                    a0.x += v.x; a0.y += v.y;
                }
                a0.x += a1.x + a2.x + a3.x;
                a0.y += a1.y + a2.y + a3.y;
                sAgg[(wl * 4 + i) * AST + lane] = split2(a0.x, a0.y);
            }
        }
        __syncthreads();

        // ---- Phase B: MMA + gates (R7 layout) ----
        int mb = tile * 64 + mhalf * 16;
        bool ok = (mb < NN);
        if (ok) {
            float gacc[3][2][4], hacc[3][2][4];
            #pragma unroll
            for (int gt = 0; gt < 3; gt++)
                #pragma unroll
                for (int j = 0; j < 2; j++) {
                    gacc[gt][j][0] = bi[gt][j][0]; gacc[gt][j][1] = bi[gt][j][1];
                    gacc[gt][j][2] = bi[gt][j][0]; gacc[gt][j][3] = bi[gt][j][1];
                    hacc[gt][j][0] = bh_[gt][j][0]; hacc[gt][j][1] = bh_[gt][j][1];
                    hacc[gt][j][2] = bh_[gt][j][0]; hacc[gt][j][3] = bh_[gt][j][1];
                }
            int row0 = mhalf * 16 + g;
            const uint2* H0 = hpsrc + (mb + g) * 32;
            const uint2* H1 = hpsrc + (mb + g + 8) * 32;
            #pragma unroll
            for (int kc = 0; kc < 4; kc++) {
                int kp0 = kc * 8 + tig, kp1 = kp0 + 4;
                uint2 a00 = sAgg[row0 * AST + kp0];
                uint2 a10 = sAgg[(row0 + 8) * AST + kp0];
                uint2 a01 = sAgg[row0 * AST + kp1];
                uint2 a11 = sAgg[(row0 + 8) * AST + kp1];
                unsigned ahi[4] = {a00.x, a10.x, a01.x, a11.x};
                unsigned alo[4] = {a00.y, a10.y, a01.y, a11.y};
                #pragma unroll
                for (int gt = 0; gt < 3; gt++)
                    #pragma unroll
                    for (int j = 0; j < 2; j++) {
                        int cb = cb0[gt][j] + kc * 8;
                        unsigned bhv[2] = {WcHi[cb], WcHi[cb + 4]};
                        unsigned blv[2] = {WcLo[cb], WcLo[cb + 4]};
                        mma_bf16(gacc[gt][j], ahi, bhv);
                        mma_bf16(gacc[gt][j], alo, bhv);
                        mma_bf16(gacc[gt][j], ahi, blv);
                    }
                uint2 h00 = H0[kp0], h10 = H1[kp0], h01 = H0[kp1], h11 = H1[kp1];
                unsigned hhi[4] = {h00.x, h10.x, h01.x, h11.x};
                unsigned hlo[4] = {h00.y, h10.y, h01.y, h11.y};
                #pragma unroll
                for (int gt = 0; gt < 3; gt++)
                    #pragma unroll
                    for (int j = 0; j < 2; j++) {
                        int cb = cb0[gt][j] + kc * 8;
                        unsigned bhv[2] = {WhHi[cb], WhHi[cb + 4]};
                        unsigned blv[2] = {WhLo[cb], WhLo[cb + 4]};
                        mma_bf16(hacc[gt][j], hhi, bhv);
                        mma_bf16(hacc[gt][j], hlo, bhv);
                        mma_bf16(hacc[gt][j], hhi, blv);
                    }
            }
            // epilogue: writes go to the NEW buffers -> no barrier needed
            #pragma unroll
            for (int j = 0; j < 2; j++)
                #pragma unroll
                for (int s = 0; s < 2; s++) {
                    int node = mb + g + 8 * s;
                    int col = wq * 16 + j * 8 + 2 * tig;
                    float2 ho = *(const float2*)(hsrc + node * HH + col);
                    float rx = sigf(gacc[0][j][2 * s]     + hacc[0][j][2 * s]);
                    float ry = sigf(gacc[0][j][2 * s + 1] + hacc[0][j][2 * s + 1]);
                    float zx = sigf(gacc[1][j][2 * s]     + hacc[1][j][2 * s]);
                    float zy = sigf(gacc[1][j][2 * s + 1] + hacc[1][j][2 * s + 1]);
                    float nx = tanhf(gacc[2][j][2 * s]     + rx * hacc[2][j][2 * s]);
                    float ny = tanhf(gacc[2][j][2 * s + 1] + ry * hacc[2][j][2 * s + 1]);
                    float ox = (1.f - zx) * nx + zx * ho.x;
                    float oy = (1.f - zy) * ny + zy * ho.y;
                    if (dorelu) { ox = fmaxf(ox, 0.f); oy = fmaxf(oy, 0.f); }
                    *(float2*)(hdst + node * HH + col) = make_float2(ox, oy);
                    hpdst[node * 32 + (col >> 1)] = split2(ox, oy);
                }
        }
    }
}

// ---------------- mean pool by graph (reads final h = buffer 0) ----------------
__global__ void k_pool(const int* __restrict__ batch) {
    int t = blockIdx.x * blockDim.x + threadIdx.x;
    if (t >= NN * 32) return;
    int n = t >> 5, L = t & 31;
    int g = __ldg(&batch[n]);
    float2 hv = ((const float2*)(d_h0 + n * HH))[L];
    atomicAdd(&d_pooled[g * HH + 2 * L], hv.x);
    atomicAdd(&d_pooled[g * HH + 2 * L + 1], hv.y);
    if (L == 0) atomicAdd(&d_cnt[g], 1.0f);
}

// ---------------- MLP head + sigmoid ----------------
__global__ void k_mlp(const float* __restrict__ W1, const float* __restrict__ b1,
                      const float* __restrict__ W2, const float* __restrict__ b2,
                      const float* __restrict__ W3, const float* __restrict__ b3,
                      float* __restrict__ out) {
    __shared__ float p[64], o1[64], o2[32];
    int g = blockIdx.x, t = threadIdx.x;
    float inv = 1.0f / fmaxf(d_cnt[g], 1.0f);
    p[t] = d_pooled[g * 64 + t] * inv;
    __syncthreads();
    float a = b1[t];
    #pragma unroll 8
    for (int k = 0; k < 64; k++) a += W1[t * 64 + k] * p[k];
    o1[t] = a;
    __syncthreads();
    if (t < 32) {
        float a2 = b2[t];
        #pragma unroll 8
        for (int k = 0; k < 64; k++) a2 += W2[t * 64 + k] * o1[k];
        o2[t] = a2;
    }
    __syncthreads();
    if (t == 0) {
        float z = b3[0];
        #pragma unroll
        for (int k = 0; k < 32; k++) z += W3[k] * o2[k];
        out[g] = 1.0f / (1.0f + __expf(-z));
    }
}

// ---------------- launch ----------------
extern "C" void kernel_launch(void* const* d_in, const int* in_sizes, int n_in,
                              void* d_out, int out_size) {
    const float* x      = (const float*)d_in[0];
    const int*   ei     = (const int*)  d_in[1];
    const int*   batch  = (const int*)  d_in[2];
    const float* Wproj  = (const float*)d_in[3];
    const float* bproj  = (const float*)d_in[4];
    const float* ggcW   = (const float*)d_in[5];
    const float* gWih   = (const float*)d_in[6];
    const float* gWhh   = (const float*)d_in[7];
    const float* gbih   = (const float*)d_in[8];
    const float* gbhh   = (const float*)d_in[9];
    const float* W1     = (const float*)d_in[10];
    const float* b1     = (const float*)d_in[11];
    const float* W2     = (const float*)d_in[12];
    const float* b2     = (const float*)d_in[13];
    const float* W3     = (const float*)d_in[14];
    const float* b3     = (const float*)d_in[15];
    float* out = (float*)d_out;

    const int L_SMEM = 4 * 192 * ST * (int)sizeof(unsigned)      // 110592 weights
                     + 64 * AST * (int)sizeof(uint2);            // 18432 sAgg -> 129024
    cudaFuncSetAttribute(k_layer, cudaFuncAttributeMaxDynamicSharedMemorySize, L_SMEM);

    k_zero<<<(NN + 255) / 256, 256>>>();
    k_count<<<(EE + 255) / 256, 256>>>(ei);
    k_scan<<<1, 1024>>>();
    k_fill<<<(EE + 255) / 256, 256>>>(ei);
    k_wc<<<dim3(8, 6), 256>>>(ggcW, gWih);
    k_proj<<<592, 256>>>(x, Wproj, bproj);

    for (int b = 0; b < 4; b++) {
        for (int l = 0; l < 2; l++) {
            int layer = b * 2 + l;
            k_layer<<<148, 512, L_SMEM>>>(layer, gWhh + b * 12288,
                                          gbih + b * 192, gbhh + b * 192,
                                          layer & 1, l == 1 ? 1 : 0);
        }
    }

    k_pool<<<(NN * 32 + 255) / 256, 256>>>(batch);
    k_mlp<<<GG, 64>>>(W1, b1, W2, b2, W3, b3, out);
}

// round 12
// speedup vs baseline: 1.5067x; 1.5067x over previous
#include <cuda_runtime.h>

#define NN 100000
#define EE 1600000
#define GG 512
#define XD 79
#define HH 64
#define ST 36   // smem [c][kp] stride in uint32: conflict-free frag loads

// ---------------- scratch (static __device__, no allocations) ----------------
__device__ float d_h[NN * HH];        // fp32 h (authoritative)
__device__ uint2 d_hp[NN * 32];       // h packed: {bf16x2 hi, bf16x2 lo} per elem-pair
__device__ uint2 d_aggp[NN * 32];     // agg packed
__device__ float d_Wc[8 * 192 * 64];
__device__ int   d_deg[NN];
__device__ int   d_rowptr[NN + 1];
__device__ int   d_cursor[NN];
__device__ int   d_col[EE + 8];
__device__ int   d_bsum[128];
__device__ float d_pooled[GG * HH];
__device__ float d_cnt[GG];

// ---------------- helpers ----------------
__device__ __forceinline__ unsigned pack_bf16(float x, float y) {
    unsigned r; asm("cvt.rn.bf16x2.f32 %0, %1, %2;" : "=r"(r) : "f"(y), "f"(x)); return r;
}
__device__ __forceinline__ float bf_lo(unsigned p) { return __uint_as_float(p << 16); }
__device__ __forceinline__ float bf_hi(unsigned p) { return __uint_as_float(p & 0xFFFF0000u); }
__device__ __forceinline__ uint2 split2(float x, float y) {
    unsigned hi = pack_bf16(x, y);
    unsigned lo = pack_bf16(x - bf_lo(hi), y - bf_hi(hi));
    return make_uint2(hi, lo);
}
__device__ __forceinline__ void mma_bf16(float* d, const unsigned* a, const unsigned* b) {
    asm("mma.sync.aligned.m16n8k16.row.col.f32.bf16.bf16.f32 "
        "{%0,%1,%2,%3}, {%4,%5,%6,%7}, {%8,%9}, {%0,%1,%2,%3};"
        : "+f"(d[0]), "+f"(d[1]), "+f"(d[2]), "+f"(d[3])
        : "r"(a[0]), "r"(a[1]), "r"(a[2]), "r"(a[3]), "r"(b[0]), "r"(b[1]));
}
__device__ __forceinline__ float sigf(float x) { return 1.0f / (1.0f + __expf(-x)); }

// ---------------- init / CSR build ----------------
__global__ void k_zero() {
    int t = blockIdx.x * blockDim.x + threadIdx.x;
    if (t < NN) d_deg[t] = 0;
    if (t < GG * HH) d_pooled[t] = 0.0f;
    if (t < GG) d_cnt[t] = 0.0f;
}

__global__ void k_count(const int* __restrict__ ei) {
    int e = blockIdx.x * blockDim.x + threadIdx.x;
    if (e < EE) atomicAdd(&d_deg[ei[EE + e]], 1);
}

// phase 1: per-block (1024) local inclusive scan -> rowptr[i+1]; block sum -> d_bsum
__global__ void k_scan1() {
    __shared__ int wsum[32];
    int b = blockIdx.x, t = threadIdx.x, lane = t & 31, wid = t >> 5;
    int i = b * 1024 + t;
    int v = (i < NN) ? d_deg[i] : 0;
    int incl = v;
    #pragma unroll
    for (int o = 1; o < 32; o <<= 1) {
        int u = __shfl_up_sync(0xffffffffu, incl, o);
        if (lane >= o) incl += u;
    }
    if (lane == 31) wsum[wid] = incl;
    __syncthreads();
    if (wid == 0) {
        int si = wsum[lane];
        #pragma unroll
        for (int o = 1; o < 32; o <<= 1) {
            int u = __shfl_up_sync(0xffffffffu, si, o);
            if (lane >= o) si += u;
        }
        wsum[lane] = si;
    }
    __syncthreads();
    int off = wid ? wsum[wid - 1] : 0;
    if (i < NN) d_rowptr[i + 1] = off + incl;
    if (t == 0) d_bsum[b] = wsum[31];
}

// phase 2: exclusive scan of the 98 block sums (one block, 128 threads)
__global__ void k_scan2(int nblocks) {
    __shared__ int wsum[4];
    int t = threadIdx.x, lane = t & 31, wid = t >> 5;
    int v = (t < nblocks) ? d_bsum[t] : 0;
    int incl = v;
    #pragma unroll
    for (int o = 1; o < 32; o <<= 1) {
        int u = __shfl_up_sync(0xffffffffu, incl, o);
        if (lane >= o) incl += u;
    }
    if (lane == 31) wsum[wid] = incl;
    __syncthreads();
    int off = 0;
    for (int j = 0; j < wid; j++) off += wsum[j];
    if (t < nblocks) d_bsum[t] = off + incl - v;  // exclusive
}

// phase 3: finalize rowptr/cursor
__global__ void k_scan3() {
    int i = blockIdx.x * blockDim.x + threadIdx.x;
    if (i < NN) {
        int fin = d_rowptr[i + 1] + d_bsum[i >> 10];
        d_rowptr[i + 1] = fin;
        d_cursor[i] = fin - d_deg[i];
    }
    if (i == 0) d_rowptr[0] = 0;
}

__global__ void k_fill(const int* __restrict__ ei) {
    int e = blockIdx.x * blockDim.x + threadIdx.x;
    if (e < EE) {
        int dst = ei[EE + e];
        int p = atomicAdd(&d_cursor[dst], 1);
        d_col[p] = ei[e];
    }
}

// ---------------- Wc[b,l] = ggc_W[b,l] @ gru_Wih[b]^T  (precompute, [c][k]) ----------------
__global__ void k_wc(const float* __restrict__ ggcW, const float* __restrict__ gWih) {
    int mat = blockIdx.x, b = mat >> 1;
    const float* W   = ggcW + mat * 4096;
    const float* Wih = gWih + b * 12288;
    __shared__ float sWt[4096];
    int t = threadIdx.x;
    for (int e = t; e < 4096; e += 256) sWt[(e & 63) * 64 + (e >> 6)] = W[e];
    __syncthreads();
    int cbase = blockIdx.y * 32;
    for (int e = t; e < 32 * 64; e += 256) {
        int c = cbase + (e >> 6), k = e & 63;
        const float* ir = Wih + c * 64;
        float s = 0.f;
        #pragma unroll 16
        for (int j = 0; j < 64; j++) s += sWt[j * 64 + k] * ir[j];
        d_Wc[mat * 12288 + c * 64 + k] = s;
    }
}

// ---------------- input projection: h = x @ Wp^T + bp ----------------
__global__ void k_proj(const float* __restrict__ x, const float* __restrict__ Wp,
                       const float* __restrict__ bp) {
    __shared__ float2 sw[XD * 32];
    int t = threadIdx.x;
    for (int e = t; e < XD * 32; e += blockDim.x) {
        int k = e >> 5, L = e & 31;
        sw[e] = make_float2(Wp[(2 * L) * XD + k], Wp[(2 * L + 1) * XD + k]);
    }
    __syncthreads();
    int lane = t & 31;
    int w = blockIdx.x * (blockDim.x >> 5) + (t >> 5);
    int nw = gridDim.x * (blockDim.x >> 5);
    float bx = bp[2 * lane], by = bp[2 * lane + 1];
    for (int n = w; n < NN; n += nw) {
        const float* xr = x + n * XD;
        float ax = bx, ay = by;
        #pragma unroll 8
        for (int k = 0; k < XD; k++) {
            float xv = __ldg(&xr[k]);
            float2 wv = sw[k * 32 + lane];
            ax += wv.x * xv;
            ay += wv.y * xv;
        }
        ((float2*)(d_h + n * HH))[lane] = make_float2(ax, ay);
        d_hp[n * 32 + lane] = split2(ax, ay);
    }
}

// ---------------- aggp[d] = split(sum h[src]) over in-edges (CSR, no atomics) ----------------
__global__ void __launch_bounds__(512) k_aggregate() {
    int lane = threadIdx.x & 31;
    int w = blockIdx.x * (blockDim.x >> 5) + (threadIdx.x >> 5);
    if (w >= NN) return;
    int e0 = d_rowptr[w], e1 = d_rowptr[w + 1];
    float2 a0 = make_float2(0.f, 0.f), a1 = make_float2(0.f, 0.f);
    float2 a2 = make_float2(0.f, 0.f), a3 = make_float2(0.f, 0.f);
    int e = e0;
    for (; e < e1 && (e & 3); e++) {
        int s = __ldg(&d_col[e]);
        float2 v = ((const float2*)(d_h + s * HH))[lane];
        a0.x += v.x; a0.y += v.y;
    }
    for (; e + 4 <= e1; e += 4) {
        int4 s4 = *reinterpret_cast<const int4*>(&d_col[e]);
        float2 v0 = ((const float2*)(d_h + s4.x * HH))[lane];
        float2 v1 = ((const float2*)(d_h + s4.y * HH))[lane];
        float2 v2 = ((const float2*)(d_h + s4.z * HH))[lane];
        float2 v3 = ((const float2*)(d_h + s4.w * HH))[lane];
        a0.x += v0.x; a0.y += v0.y;
        a1.x += v1.x; a1.y += v1.y;
        a2.x += v2.x; a2.y += v2.y;
        a3.x += v3.x; a3.y += v3.y;
    }
    for (; e < e1; e++) {
        int s = __ldg(&d_col[e]);
        float2 v = ((const float2*)(d_h + s * HH))[lane];
        a0.x += v.x; a0.y += v.y;
    }
    a0.x += a1.x + a2.x + a3.x;
    a0.y += a1.y + a2.y + a3.y;
    d_aggp[w * 32 + lane] = split2(a0.x, a0.y);
}

// ---------------- fused layer: gi = aggh@Wc+bih, gh = h@Whh^T+bhh, gates, h update ----------------
// 256 threads (8 warps), 32-node tiles: mhalf = wl>>2 in {0,1}, wq = wl&3 (n16 per gate).
// Target 2 blocks/SM (2 x 110.6 KB smem) -> 32 warps/SM.
__global__ void __launch_bounds__(256, 2) k_gru(int mat, const float* __restrict__ Whh,
                                                const float* __restrict__ bih,
                                                const float* __restrict__ bhh, int dorelu) {
    extern __shared__ unsigned smu[];
    unsigned* WcHi = smu;
    unsigned* WcLo = smu + 192 * ST;
    unsigned* WhHi = smu + 2 * 192 * ST;
    unsigned* WhLo = smu + 3 * 192 * ST;
    const float* Wc = d_Wc + mat * 12288;
    int t = threadIdx.x;
    for (int e = t; e < 192 * 32; e += 256) {
        int c = e >> 5, kp = e & 31;
        float a0 = Wc[c * 64 + 2 * kp], a1 = Wc[c * 64 + 2 * kp + 1];
        uint2 pa = split2(a0, a1);
        WcHi[c * ST + kp] = pa.x;
        WcLo[c * ST + kp] = pa.y;
        float b0 = Whh[c * 64 + 2 * kp], b1 = Whh[c * 64 + 2 * kp + 1];
        uint2 pb = split2(b0, b1);
        WhHi[c * ST + kp] = pb.x;
        WhLo[c * ST + kp] = pb.y;
    }
    __syncthreads();
    int lane = t & 31, wl = t >> 5;
    int g = lane >> 2, tig = lane & 3;
    int mhalf = wl >> 2, wq = wl & 3;

    int cb0[3][2];
    #pragma unroll
    for (int gt = 0; gt < 3; gt++)
        #pragma unroll
        for (int j = 0; j < 2; j++)
            cb0[gt][j] = (gt * 64 + wq * 16 + j * 8 + g) * ST + tig;

    float bi[3][2][2], bh_[3][2][2];
    #pragma unroll
    for (int gt = 0; gt < 3; gt++)
        #pragma unroll
        for (int j = 0; j < 2; j++) {
            int col = gt * 64 + wq * 16 + j * 8 + 2 * tig;
            bi[gt][j][0] = __ldg(&bih[col]); bi[gt][j][1] = __ldg(&bih[col + 1]);
            bh_[gt][j][0] = __ldg(&bhh[col]); bh_[gt][j][1] = __ldg(&bhh[col + 1]);
        }

    for (int tile = blockIdx.x; tile * 32 < NN; tile += gridDim.x) {
        int mb = tile * 32 + mhalf * 16;   // NN % 32 == 0 -> always in range
        float gacc[3][2][4], hacc[3][2][4];
        #pragma unroll
        for (int gt = 0; gt < 3; gt++)
            #pragma unroll
            for (int j = 0; j < 2; j++) {
                gacc[gt][j][0] = bi[gt][j][0]; gacc[gt][j][1] = bi[gt][j][1];
                gacc[gt][j][2] = bi[gt][j][0]; gacc[gt][j][3] = bi[gt][j][1];
                hacc[gt][j][0] = bh_[gt][j][0]; hacc[gt][j][1] = bh_[gt][j][1];
                hacc[gt][j][2] = bh_[gt][j][0]; hacc[gt][j][3] = bh_[gt][j][1];
            }
        const uint2* A0 = d_aggp + (mb + g) * 32;
        const uint2* A1 = d_aggp + (mb + g + 8) * 32;
        const uint2* H0 = d_hp + (mb + g) * 32;
        const uint2* H1 = d_hp + (mb + g + 8) * 32;
        #pragma unroll
        for (int kc = 0; kc < 4; kc++) {
            int kp0 = kc * 8 + tig, kp1 = kp0 + 4;
            uint2 a00 = A0[kp0], a10 = A1[kp0], a01 = A0[kp1], a11 = A1[kp1];
            unsigned ahi[4] = {a00.x, a10.x, a01.x, a11.x};
            unsigned alo[4] = {a00.y, a10.y, a01.y, a11.y};
            #pragma unroll
            for (int gt = 0; gt < 3; gt++)
                #pragma unroll
                for (int j = 0; j < 2; j++) {
                    int cb = cb0[gt][j] + kc * 8;
                    unsigned bhv[2] = {WcHi[cb], WcHi[cb + 4]};
                    unsigned blv[2] = {WcLo[cb], WcLo[cb + 4]};
                    mma_bf16(gacc[gt][j], ahi, bhv);
                    mma_bf16(gacc[gt][j], alo, bhv);
                    mma_bf16(gacc[gt][j], ahi, blv);
                }
            uint2 h00 = H0[kp0], h10 = H1[kp0], h01 = H0[kp1], h11 = H1[kp1];
            unsigned hhi[4] = {h00.x, h10.x, h01.x, h11.x};
            unsigned hlo[4] = {h00.y, h10.y, h01.y, h11.y};
            #pragma unroll
            for (int gt = 0; gt < 3; gt++)
                #pragma unroll
                for (int j = 0; j < 2; j++) {
                    int cb = cb0[gt][j] + kc * 8;
                    unsigned bhv[2] = {WhHi[cb], WhHi[cb + 4]};
                    unsigned blv[2] = {WhLo[cb], WhLo[cb + 4]};
                    mma_bf16(hacc[gt][j], hhi, bhv);
                    mma_bf16(hacc[gt][j], hlo, bhv);
                    mma_bf16(hacc[gt][j], hhi, blv);
                }
        }
        __syncthreads();  // all packed-h reads done before any h/hp writes
        #pragma unroll
        for (int j = 0; j < 2; j++)
            #pragma unroll
            for (int s = 0; s < 2; s++) {
                int node = mb + g + 8 * s;
                int col = wq * 16 + j * 8 + 2 * tig;
                float2 ho = *(const float2*)(d_h + node * HH + col);
                float rx = sigf(gacc[0][j][2 * s]     + hacc[0][j][2 * s]);
                float ry = sigf(gacc[0][j][2 * s + 1] + hacc[0][j][2 * s + 1]);
                float zx = sigf(gacc[1][j][2 * s]     + hacc[1][j][2 * s]);
                float zy = sigf(gacc[1][j][2 * s + 1] + hacc[1][j][2 * s + 1]);
                float nx = tanhf(gacc[2][j][2 * s]     + rx * hacc[2][j][2 * s]);
                float ny = tanhf(gacc[2][j][2 * s + 1] + ry * hacc[2][j][2 * s + 1]);
                float ox = (1.f - zx) * nx + zx * ho.x;
                float oy = (1.f - zy) * ny + zy * ho.y;
                if (dorelu) { ox = fmaxf(ox, 0.f); oy = fmaxf(oy, 0.f); }
                *(float2*)(d_h + node * HH + col) = make_float2(ox, oy);
                d_hp[node * 32 + (col >> 1)] = split2(ox, oy);
            }
        __syncthreads();  // h writes done before next tile's weight-smem reuse is safe
    }
}

// ---------------- mean pool by graph (batch sorted -> run-length segmented) ----------------
__global__ void k_pool(const int* __restrict__ batch) {
    int warp = blockIdx.x * (blockDim.x >> 5) + (threadIdx.x >> 5);
    int lane = threadIdx.x & 31;
    int base = warp * 8;
    if (base >= NN) return;
    int end = base + 8 < NN ? base + 8 : NN;
    int curg = __ldg(&batch[base]);
    float sx = 0.f, sy = 0.f;
    int cnt = 0;
    for (int n = base; n < end; n++) {
        int g = __ldg(&batch[n]);
        if (g != curg) {
            atomicAdd(&d_pooled[curg * HH + 2 * lane], sx);
            atomicAdd(&d_pooled[curg * HH + 2 * lane + 1], sy);
            if (lane == 0) atomicAdd(&d_cnt[curg], (float)cnt);
            curg = g; sx = 0.f; sy = 0.f; cnt = 0;
        }
        float2 hv = ((const float2*)(d_h + n * HH))[lane];
        sx += hv.x; sy += hv.y; cnt++;
    }
    atomicAdd(&d_pooled[curg * HH + 2 * lane], sx);
    atomicAdd(&d_pooled[curg * HH + 2 * lane + 1], sy);
    if (lane == 0) atomicAdd(&d_cnt[curg], (float)cnt);
}

// ---------------- MLP head + sigmoid ----------------
__global__ void k_mlp(const float* __restrict__ W1, const float* __restrict__ b1,
                      const float* __restrict__ W2, const float* __restrict__ b2,
                      const float* __restrict__ W3, const float* __restrict__ b3,
                      float* __restrict__ out) {
    __shared__ float p[64], o1[64], o2[32];
    int g = blockIdx.x, t = threadIdx.x;
    float inv = 1.0f / fmaxf(d_cnt[g], 1.0f);
    p[t] = d_pooled[g * 64 + t] * inv;
    __syncthreads();
    float a = b1[t];
    #pragma unroll 8
    for (int k = 0; k < 64; k++) a += W1[t * 64 + k] * p[k];
    o1[t] = a;
    __syncthreads();
    if (t < 32) {
        float a2 = b2[t];
        #pragma unroll 8
        for (int k = 0; k < 64; k++) a2 += W2[t * 64 + k] * o1[k];
        o2[t] = a2;
    }
    __syncthreads();
    if (t == 0) {
        float z = b3[0];
        #pragma unroll
        for (int k = 0; k < 32; k++) z += W3[k] * o2[k];
        out[g] = 1.0f / (1.0f + __expf(-z));
    }
}

// ---------------- launch ----------------
extern "C" void kernel_launch(void* const* d_in, const int* in_sizes, int n_in,
                              void* d_out, int out_size) {
    const float* x      = (const float*)d_in[0];
    const int*   ei     = (const int*)  d_in[1];
    const int*   batch  = (const int*)  d_in[2];
    const float* Wproj  = (const float*)d_in[3];
    const float* bproj  = (const float*)d_in[4];
    const float* ggcW   = (const float*)d_in[5];
    const float* gWih   = (const float*)d_in[6];
    const float* gWhh   = (const float*)d_in[7];
    const float* gbih   = (const float*)d_in[8];
    const float* gbhh   = (const float*)d_in[9];
    const float* W1     = (const float*)d_in[10];
    const float* b1     = (const float*)d_in[11];
    const float* W2     = (const float*)d_in[12];
    const float* b2     = (const float*)d_in[13];
    const float* W3     = (const float*)d_in[14];
    const float* b3     = (const float*)d_in[15];
    float* out = (float*)d_out;

    const int GRU_SMEM = 4 * 192 * ST * (int)sizeof(unsigned);  // 110592
    cudaFuncSetAttribute(k_gru, cudaFuncAttributeMaxDynamicSharedMemorySize, GRU_SMEM);

    const int NSCAN = (NN + 1023) / 1024;  // 98

    k_zero<<<(NN + 255) / 256, 256>>>();
    k_count<<<(EE + 255) / 256, 256>>>(ei);
    k_scan1<<<NSCAN, 1024>>>();
    k_scan2<<<1, 128>>>(NSCAN);
    k_scan3<<<(NN + 1023) / 1024, 1024>>>();
    k_fill<<<(EE + 255) / 256, 256>>>(ei);
    k_wc<<<dim3(8, 6), 256>>>(ggcW, gWih);
    k_proj<<<592, 256>>>(x, Wproj, bproj);

    for (int b = 0; b < 4; b++) {
        for (int l = 0; l < 2; l++) {
            k_aggregate<<<(NN + 15) / 16, 512>>>();
            k_gru<<<296, 256, GRU_SMEM>>>(b * 2 + l, gWhh + b * 12288,
                                          gbih + b * 192, gbhh + b * 192, l == 1 ? 1 : 0);
        }
    }

    k_pool<<<(NN / 8 + 7) / 8 + 1, 256>>>(batch);
    k_mlp<<<GG, 64>>>(W1, b1, W2, b2, W3, b3, out);
}

// round 13
// speedup vs baseline: 1.5146x; 1.0052x over previous
#include <cuda_runtime.h>

#define NN 100000
#define EE 1600000
#define GG 512
#define XD 79
#define HH 64
#define ST 36   // smem [c][kp] stride in uint32: conflict-free frag loads

// ---------------- scratch (static __device__, no allocations) ----------------
__device__ float d_h[NN * HH];        // fp32 h (authoritative)
__device__ uint2 d_hp[NN * 32];       // h packed: {bf16x2 hi, bf16x2 lo} per elem-pair
__device__ uint2 d_aggp[NN * 32];     // agg packed
__device__ float d_Wc[8 * 192 * 64];
__device__ uint2 d_WcP[8 * 6144];     // pre-split Wc (hi,lo) per elem-pair
__device__ uint2 d_WhP[4 * 6144];     // pre-split Whh
__device__ int   d_deg[NN];
__device__ int   d_rowptr[NN + 1];
__device__ int   d_cursor[NN];
__device__ int   d_col[EE + 8];
__device__ int   d_bsum[128];
__device__ float d_pooled[GG * HH];
__device__ float d_cnt[GG];

// ---------------- helpers ----------------
__device__ __forceinline__ unsigned pack_bf16(float x, float y) {
    unsigned r; asm("cvt.rn.bf16x2.f32 %0, %1, %2;" : "=r"(r) : "f"(y), "f"(x)); return r;
}
__device__ __forceinline__ float bf_lo(unsigned p) { return __uint_as_float(p << 16); }
__device__ __forceinline__ float bf_hi(unsigned p) { return __uint_as_float(p & 0xFFFF0000u); }
__device__ __forceinline__ uint2 split2(float x, float y) {
    unsigned hi = pack_bf16(x, y);
    unsigned lo = pack_bf16(x - bf_lo(hi), y - bf_hi(hi));
    return make_uint2(hi, lo);
}
__device__ __forceinline__ void mma_bf16(float* d, const unsigned* a, const unsigned* b) {
    asm("mma.sync.aligned.m16n8k16.row.col.f32.bf16.bf16.f32 "
        "{%0,%1,%2,%3}, {%4,%5,%6,%7}, {%8,%9}, {%0,%1,%2,%3};"
        : "+f"(d[0]), "+f"(d[1]), "+f"(d[2]), "+f"(d[3])
        : "r"(a[0]), "r"(a[1]), "r"(a[2]), "r"(a[3]), "r"(b[0]), "r"(b[1]));
}
__device__ __forceinline__ float sigf(float x) { return 1.0f / (1.0f + __expf(-x)); }

// ---------------- CSR build ----------------
__global__ void k_count(const int* __restrict__ ei) {
    int e = blockIdx.x * blockDim.x + threadIdx.x;
    if (e < EE) atomicAdd(&d_deg[ei[EE + e]], 1);
}

// phase 1: per-block (1024) local inclusive scan -> rowptr[i+1]; block sum -> d_bsum
__global__ void k_scan1() {
    __shared__ int wsum[32];
    int b = blockIdx.x, t = threadIdx.x, lane = t & 31, wid = t >> 5;
    int i = b * 1024 + t;
    int v = (i < NN) ? d_deg[i] : 0;
    int incl = v;
    #pragma unroll
    for (int o = 1; o < 32; o <<= 1) {
        int u = __shfl_up_sync(0xffffffffu, incl, o);
        if (lane >= o) incl += u;
    }
    if (lane == 31) wsum[wid] = incl;
    __syncthreads();
    if (wid == 0) {
        int si = wsum[lane];
        #pragma unroll
        for (int o = 1; o < 32; o <<= 1) {
            int u = __shfl_up_sync(0xffffffffu, si, o);
            if (lane >= o) si += u;
        }
        wsum[lane] = si;
    }
    __syncthreads();
    int off = wid ? wsum[wid - 1] : 0;
    if (i < NN) d_rowptr[i + 1] = off + incl;
    if (t == 0) d_bsum[b] = wsum[31];
}

// phase 2: exclusive scan of the block sums (one block, 128 threads)
__global__ void k_scan2(int nblocks) {
    __shared__ int wsum[4];
    int t = threadIdx.x, lane = t & 31, wid = t >> 5;
    int v = (t < nblocks) ? d_bsum[t] : 0;
    int incl = v;
    #pragma unroll
    for (int o = 1; o < 32; o <<= 1) {
        int u = __shfl_up_sync(0xffffffffu, incl, o);
        if (lane >= o) incl += u;
    }
    if (lane == 31) wsum[wid] = incl;
    __syncthreads();
    int off = 0;
    for (int j = 0; j < wid; j++) off += wsum[j];
    if (t < nblocks) d_bsum[t] = off + incl - v;  // exclusive
}

// phase 3: finalize rowptr/cursor
__global__ void k_scan3() {
    int i = blockIdx.x * blockDim.x + threadIdx.x;
    if (i < NN) {
        int fin = d_rowptr[i + 1] + d_bsum[i >> 10];
        d_rowptr[i + 1] = fin;
        d_cursor[i] = fin - d_deg[i];
    }
    if (i == 0) d_rowptr[0] = 0;
}

__global__ void k_fill(const int* __restrict__ ei) {
    int e = blockIdx.x * blockDim.x + threadIdx.x;
    if (e < EE) {
        int dst = ei[EE + e];
        int p = atomicAdd(&d_cursor[dst], 1);
        d_col[p] = ei[e];
    }
}

// ---------------- Wc[b,l] = ggc_W[b,l] @ gru_Wih[b]^T  (precompute, [c][k]) ----------------
__global__ void k_wc(const float* __restrict__ ggcW, const float* __restrict__ gWih) {
    int mat = blockIdx.x, b = mat >> 1;
    const float* W   = ggcW + mat * 4096;
    const float* Wih = gWih + b * 12288;
    __shared__ float sWt[4096];
    int t = threadIdx.x;
    for (int e = t; e < 4096; e += 256) sWt[(e & 63) * 64 + (e >> 6)] = W[e];
    __syncthreads();
    int cbase = blockIdx.y * 32;
    for (int e = t; e < 32 * 64; e += 256) {
        int c = cbase + (e >> 6), k = e & 63;
        const float* ir = Wih + c * 64;
        float s = 0.f;
        #pragma unroll 16
        for (int j = 0; j < 64; j++) s += sWt[j * 64 + k] * ir[j];
        d_Wc[mat * 12288 + c * 64 + k] = s;
    }
}

// ---------------- pre-split all weights to packed hi/lo planes ----------------
__global__ void k_wsplit(const float* __restrict__ gWhh) {
    int m = blockIdx.x;   // 0..7 -> Wc mats, 8..11 -> Whh blocks
    int t = threadIdx.x;
    if (m < 8) {
        const float* src = d_Wc + m * 12288;
        uint2* dst = d_WcP + m * 6144;
        for (int e = t; e < 6144; e += 256)
            dst[e] = split2(src[2 * e], src[2 * e + 1]);
    } else {
        const float* src = gWhh + (m - 8) * 12288;
        uint2* dst = d_WhP + (m - 8) * 6144;
        for (int e = t; e < 6144; e += 256)
            dst[e] = split2(src[2 * e], src[2 * e + 1]);
    }
}

// ---------------- input projection: h = x @ Wp^T + bp ----------------
__global__ void k_proj(const float* __restrict__ x, const float* __restrict__ Wp,
                       const float* __restrict__ bp) {
    __shared__ float2 sw[XD * 32];
    int t = threadIdx.x;
    for (int e = t; e < XD * 32; e += blockDim.x) {
        int k = e >> 5, L = e & 31;
        sw[e] = make_float2(Wp[(2 * L) * XD + k], Wp[(2 * L + 1) * XD + k]);
    }
    __syncthreads();
    int lane = t & 31;
    int w = blockIdx.x * (blockDim.x >> 5) + (t >> 5);
    int nw = gridDim.x * (blockDim.x >> 5);
    float bx = bp[2 * lane], by = bp[2 * lane + 1];
    for (int n = w; n < NN; n += nw) {
        const float* xr = x + n * XD;
        float ax = bx, ay = by;
        #pragma unroll 8
        for (int k = 0; k < XD; k++) {
            float xv = __ldg(&xr[k]);
            float2 wv = sw[k * 32 + lane];
            ax += wv.x * xv;
            ay += wv.y * xv;
        }
        ((float2*)(d_h + n * HH))[lane] = make_float2(ax, ay);
        d_hp[n * 32 + lane] = split2(ax, ay);
    }
}

// ---------------- aggp[d] = split(sum h[src]) over in-edges (CSR, no atomics) ----------------
__global__ void __launch_bounds__(512) k_aggregate() {
    int lane = threadIdx.x & 31;
    int w = blockIdx.x * (blockDim.x >> 5) + (threadIdx.x >> 5);
    if (w >= NN) return;
    int e0 = d_rowptr[w], e1 = d_rowptr[w + 1];
    float2 a0 = make_float2(0.f, 0.f), a1 = make_float2(0.f, 0.f);
    float2 a2 = make_float2(0.f, 0.f), a3 = make_float2(0.f, 0.f);
    int e = e0;
    for (; e < e1 && (e & 3); e++) {
        int s = __ldg(&d_col[e]);
        float2 v = ((const float2*)(d_h + s * HH))[lane];
        a0.x += v.x; a0.y += v.y;
    }
    for (; e + 4 <= e1; e += 4) {
        int4 s4 = *reinterpret_cast<const int4*>(&d_col[e]);
        float2 v0 = ((const float2*)(d_h + s4.x * HH))[lane];
        float2 v1 = ((const float2*)(d_h + s4.y * HH))[lane];
        float2 v2 = ((const float2*)(d_h + s4.z * HH))[lane];
        float2 v3 = ((const float2*)(d_h + s4.w * HH))[lane];
        a0.x += v0.x; a0.y += v0.y;
        a1.x += v1.x; a1.y += v1.y;
        a2.x += v2.x; a2.y += v2.y;
        a3.x += v3.x; a3.y += v3.y;
    }
    for (; e < e1; e++) {
        int s = __ldg(&d_col[e]);
        float2 v = ((const float2*)(d_h + s * HH))[lane];
        a0.x += v.x; a0.y += v.y;
    }
    a0.x += a1.x + a2.x + a3.x;
    a0.y += a1.y + a2.y + a3.y;
    d_aggp[w * 32 + lane] = split2(a0.x, a0.y);
}

// ---------------- fused layer: gi = aggh@Wc+bih, gh = h@Whh^T+bhh, gates, h update ----------------
// 256 threads (8 warps), 32-node tiles, 2 blocks/SM. Weights pre-split (pure copy prologue).
__global__ void __launch_bounds__(256, 2) k_gru(int mat, int bb,
                                                const float* __restrict__ bih,
                                                const float* __restrict__ bhh, int dorelu) {
    extern __shared__ unsigned smu[];
    unsigned* WcHi = smu;
    unsigned* WcLo = smu + 192 * ST;
    unsigned* WhHi = smu + 2 * 192 * ST;
    unsigned* WhLo = smu + 3 * 192 * ST;
    const uint2* WcP = d_WcP + mat * 6144;
    const uint2* WhP = d_WhP + bb * 6144;
    int t = threadIdx.x;
    for (int e = t; e < 6144; e += 256) {
        int c = e >> 5, kp = e & 31;
        uint2 pa = WcP[e];
        WcHi[c * ST + kp] = pa.x;
        WcLo[c * ST + kp] = pa.y;
        uint2 pb = WhP[e];
        WhHi[c * ST + kp] = pb.x;
        WhLo[c * ST + kp] = pb.y;
    }
    __syncthreads();
    int lane = t & 31, wl = t >> 5;
    int g = lane >> 2, tig = lane & 3;
    int mhalf = wl >> 2, wq = wl & 3;

    int cb0[3][2];
    #pragma unroll
    for (int gt = 0; gt < 3; gt++)
        #pragma unroll
        for (int j = 0; j < 2; j++)
            cb0[gt][j] = (gt * 64 + wq * 16 + j * 8 + g) * ST + tig;

    float bi[3][2][2], bh_[3][2][2];
    #pragma unroll
    for (int gt = 0; gt < 3; gt++)
        #pragma unroll
        for (int j = 0; j < 2; j++) {
            int col = gt * 64 + wq * 16 + j * 8 + 2 * tig;
            bi[gt][j][0] = __ldg(&bih[col]); bi[gt][j][1] = __ldg(&bih[col + 1]);
            bh_[gt][j][0] = __ldg(&bhh[col]); bh_[gt][j][1] = __ldg(&bhh[col + 1]);
        }

    for (int tile = blockIdx.x; tile * 32 < NN; tile += gridDim.x) {
        int mb = tile * 32 + mhalf * 16;   // NN % 32 == 0 -> always in range
        float gacc[3][2][4], hacc[3][2][4];
        #pragma unroll
        for (int gt = 0; gt < 3; gt++)
            #pragma unroll
            for (int j = 0; j < 2; j++) {
                gacc[gt][j][0] = bi[gt][j][0]; gacc[gt][j][1] = bi[gt][j][1];
                gacc[gt][j][2] = bi[gt][j][0]; gacc[gt][j][3] = bi[gt][j][1];
                hacc[gt][j][0] = bh_[gt][j][0]; hacc[gt][j][1] = bh_[gt][j][1];
                hacc[gt][j][2] = bh_[gt][j][0]; hacc[gt][j][3] = bh_[gt][j][1];
            }
        const uint2* A0 = d_aggp + (mb + g) * 32;
        const uint2* A1 = d_aggp + (mb + g + 8) * 32;
        const uint2* H0 = d_hp + (mb + g) * 32;
        const uint2* H1 = d_hp + (mb + g + 8) * 32;
        #pragma unroll
        for (int kc = 0; kc < 4; kc++) {
            int kp0 = kc * 8 + tig, kp1 = kp0 + 4;
            uint2 a00 = A0[kp0], a10 = A1[kp0], a01 = A0[kp1], a11 = A1[kp1];
            unsigned ahi[4] = {a00.x, a10.x, a01.x, a11.x};
            unsigned alo[4] = {a00.y, a10.y, a01.y, a11.y};
            #pragma unroll
            for (int gt = 0; gt < 3; gt++)
                #pragma unroll
                for (int j = 0; j < 2; j++) {
                    int cb = cb0[gt][j] + kc * 8;
                    unsigned bhv[2] = {WcHi[cb], WcHi[cb + 4]};
                    unsigned blv[2] = {WcLo[cb], WcLo[cb + 4]};
                    mma_bf16(gacc[gt][j], ahi, bhv);
                    mma_bf16(gacc[gt][j], alo, bhv);
                    mma_bf16(gacc[gt][j], ahi, blv);
                }
            uint2 h00 = H0[kp0], h10 = H1[kp0], h01 = H0[kp1], h11 = H1[kp1];
            unsigned hhi[4] = {h00.x, h10.x, h01.x, h11.x};
            unsigned hlo[4] = {h00.y, h10.y, h01.y, h11.y};
            #pragma unroll
            for (int gt = 0; gt < 3; gt++)
                #pragma unroll
                for (int j = 0; j < 2; j++) {
                    int cb = cb0[gt][j] + kc * 8;
                    unsigned bhv[2] = {WhHi[cb], WhHi[cb + 4]};
                    unsigned blv[2] = {WhLo[cb], WhLo[cb + 4]};
                    mma_bf16(hacc[gt][j], hhi, bhv);
                    mma_bf16(hacc[gt][j], hlo, bhv);
                    mma_bf16(hacc[gt][j], hhi, blv);
                }
        }
        // hoist ho loads before barrier (reads are safe pre-barrier; hides L2 latency)
        float2 ho[2][2];
        #pragma unroll
        for (int j = 0; j < 2; j++)
            #pragma unroll
            for (int s = 0; s < 2; s++)
                ho[j][s] = *(const float2*)(d_h + (mb + g + 8 * s) * HH + wq * 16 + j * 8 + 2 * tig);
        __syncthreads();  // all packed-h / h reads done before any h/hp writes
        #pragma unroll
        for (int j = 0; j < 2; j++)
            #pragma unroll
            for (int s = 0; s < 2; s++) {
                int node = mb + g + 8 * s;
                int col = wq * 16 + j * 8 + 2 * tig;
                float rx = sigf(gacc[0][j][2 * s]     + hacc[0][j][2 * s]);
                float ry = sigf(gacc[0][j][2 * s + 1] + hacc[0][j][2 * s + 1]);
                float zx = sigf(gacc[1][j][2 * s]     + hacc[1][j][2 * s]);
                float zy = sigf(gacc[1][j][2 * s + 1] + hacc[1][j][2 * s + 1]);
                float nx = tanhf(gacc[2][j][2 * s]     + rx * hacc[2][j][2 * s]);
                float ny = tanhf(gacc[2][j][2 * s + 1] + ry * hacc[2][j][2 * s + 1]);
                float ox = (1.f - zx) * nx + zx * ho[j][s].x;
                float oy = (1.f - zy) * ny + zy * ho[j][s].y;
                if (dorelu) { ox = fmaxf(ox, 0.f); oy = fmaxf(oy, 0.f); }
                *(float2*)(d_h + node * HH + col) = make_float2(ox, oy);
                d_hp[node * 32 + (col >> 1)] = split2(ox, oy);
            }
        // no trailing barrier: weights are read-only; next tile touches disjoint rows
    }
}

// ---------------- mean pool by graph (batch sorted -> run-length segmented) ----------------
__global__ void k_pool(const int* __restrict__ batch) {
    int warp = blockIdx.x * (blockDim.x >> 5) + (threadIdx.x >> 5);
    int lane = threadIdx.x & 31;
    int base = warp * 8;
    if (base >= NN) return;
    int end = base + 8 < NN ? base + 8 : NN;
    int curg = __ldg(&batch[base]);
    float sx = 0.f, sy = 0.f;
    int cnt = 0;
    for (int n = base; n < end; n++) {
        int g = __ldg(&batch[n]);
        if (g != curg) {
            atomicAdd(&d_pooled[curg * HH + 2 * lane], sx);
            atomicAdd(&d_pooled[curg * HH + 2 * lane + 1], sy);
            if (lane == 0) atomicAdd(&d_cnt[curg], (float)cnt);
            curg = g; sx = 0.f; sy = 0.f; cnt = 0;
        }
        float2 hv = ((const float2*)(d_h + n * HH))[lane];
        sx += hv.x; sy += hv.y; cnt++;
    }
    atomicAdd(&d_pooled[curg * HH + 2 * lane], sx);
    atomicAdd(&d_pooled[curg * HH + 2 * lane + 1], sy);
    if (lane == 0) atomicAdd(&d_cnt[curg], (float)cnt);
}

// ---------------- MLP head + sigmoid ----------------
__global__ void k_mlp(const float* __restrict__ W1, const float* __restrict__ b1,
                      const float* __restrict__ W2, const float* __restrict__ b2,
                      const float* __restrict__ W3, const float* __restrict__ b3,
                      float* __restrict__ out) {
    __shared__ float p[64], o1[64], o2[32];
    int g = blockIdx.x, t = threadIdx.x;
    float inv = 1.0f / fmaxf(d_cnt[g], 1.0f);
    p[t] = d_pooled[g * 64 + t] * inv;
    __syncthreads();
    float a = b1[t];
    #pragma unroll 8
    for (int k = 0; k < 64; k++) a += W1[t * 64 + k] * p[k];
    o1[t] = a;
    __syncthreads();
    if (t < 32) {
        float a2 = b2[t];
        #pragma unroll 8
        for (int k = 0; k < 64; k++) a2 += W2[t * 64 + k] * o1[k];
        o2[t] = a2;
    }
    __syncthreads();
    if (t == 0) {
        float z = b3[0];
        #pragma unroll
        for (int k = 0; k < 32; k++) z += W3[k] * o2[k];
        out[g] = 1.0f / (1.0f + __expf(-z));
    }
}

// ---------------- launch ----------------
extern "C" void kernel_launch(void* const* d_in, const int* in_sizes, int n_in,
                              void* d_out, int out_size) {
    const float* x      = (const float*)d_in[0];
    const int*   ei     = (const int*)  d_in[1];
    const int*   batch  = (const int*)  d_in[2];
    const float* Wproj  = (const float*)d_in[3];
    const float* bproj  = (const float*)d_in[4];
    const float* ggcW   = (const float*)d_in[5];
    const float* gWih   = (const float*)d_in[6];
    const float* gWhh   = (const float*)d_in[7];
    const float* gbih   = (const float*)d_in[8];
    const float* gbhh   = (const float*)d_in[9];
    const float* W1     = (const float*)d_in[10];
    const float* b1     = (const float*)d_in[11];
    const float* W2     = (const float*)d_in[12];
    const float* b2     = (const float*)d_in[13];
    const float* W3     = (const float*)d_in[14];
    const float* b3     = (const float*)d_in[15];
    float* out = (float*)d_out;

    const int GRU_SMEM = 4 * 192 * ST * (int)sizeof(unsigned);  // 110592
    cudaFuncSetAttribute(k_gru, cudaFuncAttributeMaxDynamicSharedMemorySize, GRU_SMEM);

    void *p_deg, *p_pooled, *p_cnt;
    cudaGetSymbolAddress(&p_deg, d_deg);
    cudaGetSymbolAddress(&p_pooled, d_pooled);
    cudaGetSymbolAddress(&p_cnt, d_cnt);

    // fork a side stream into the capture for the weight/proj chain
    cudaStream_t s2;
    cudaStreamCreateWithFlags(&s2, cudaStreamNonBlocking);
    cudaEvent_t eF, eJ;
    cudaEventCreateWithFlags(&eF, cudaEventDisableTiming);
    cudaEventCreateWithFlags(&eJ, cudaEventDisableTiming);

    cudaEventRecord(eF, 0);
    cudaStreamWaitEvent(s2, eF, 0);

    // side stream: weights + projection + pool-buffer zeroing
    cudaMemsetAsync(p_pooled, 0, GG * HH * sizeof(float), s2);
    cudaMemsetAsync(p_cnt, 0, GG * sizeof(float), s2);
    k_wc<<<dim3(8, 6), 256, 0, s2>>>(ggcW, gWih);
    k_wsplit<<<12, 256, 0, s2>>>(gWhh);
    k_proj<<<592, 256, 0, s2>>>(x, Wproj, bproj);
    cudaEventRecord(eJ, s2);

    // main stream: CSR build
    const int NSCAN = (NN + 1023) / 1024;  // 98
    cudaMemsetAsync(p_deg, 0, NN * sizeof(int), 0);
    k_count<<<(EE + 255) / 256, 256>>>(ei);
    k_scan1<<<NSCAN, 1024>>>();
    k_scan2<<<1, 128>>>(NSCAN);
    k_scan3<<<(NN + 1023) / 1024, 1024>>>();
    k_fill<<<(EE + 255) / 256, 256>>>(ei);

    cudaStreamWaitEvent(0, eJ, 0);  // join

    for (int b = 0; b < 4; b++) {
        for (int l = 0; l < 2; l++) {
            k_aggregate<<<(NN + 15) / 16, 512>>>();
            k_gru<<<296, 256, GRU_SMEM>>>(b * 2 + l, b,
                                          gbih + b * 192, gbhh + b * 192, l == 1 ? 1 : 0);
        }
    }

    k_pool<<<(NN / 8 + 7) / 8 + 1, 256>>>(batch);
    k_mlp<<<GG, 64>>>(W1, b1, W2, b2, W3, b3, out);
    // s2/eF/eJ intentionally not destroyed: destroying capture-participating
    // resources mid-capture invalidates the graph; few calls -> negligible leak.
}